// round 13
// baseline (speedup 1.0000x reference)
#include <cuda_runtime.h>
#include <math_constants.h>
#include <stdint.h>

// PQHead: out[b, m*6+d] = codebooks[m, argmax_k <x[b,m*6:...], cb[m,k,:]>, d]
// (forward value of the straight-through estimator == discrete codeword)
//
// FROZEN NUMERICS: per-m dot = x_d0*c_d0 then fma.rn chain d=1..5, argmax
// exact FSETP strict-'>' (FIRST-max tie rule). Zero flips vs JAX reference.
//
// LESSONS:
//  R3/R4 spills, R7 f32x2 half-rate, R12 cp.async (bank conflicts + LSU) all
//  banned. R9 best (63us): L1TEX 84% = wall; budget/pair = 1.5 LDS + 1.1 LDG
//  + 1.1 STG, the latter two pure sector redundancy from 24B-stride 8B ops.
//  R13: thread owns an m-PAIR (48B, 16B-aligned) -> LDG.128/STG.128, zero
//  redundant sectors; codebook repacked as 3x float4[k][mpair].

#define B_ROWS   32768
#define M_SUB    128
#define QM       16                      // m's per block = 8 m-pairs
#define NMP      8                       // m-pairs per block
#define NGRP     (M_SUB / QM)            // 8
#define K_CODES  32
#define D_SUB    6
#define DIM      768
#define TPB      256                     // 32 row-groups x 8 m-pairs
#define TILE_ROWS (TPB / NMP)            // 32
#define NTILES   (B_ROWS / TILE_ROWS)    // 1024 per group
#define BLK_PER_G 74                     // 8 x 74 = 592 = 4/SM
#define NBLOCKS  (NGRP * BLK_PER_G)

__global__ void __launch_bounds__(TPB, 4)
pq_head_kernel(const float* __restrict__ x,
               const float* __restrict__ cb,
               float* __restrict__ out)
{
    // Packed codebook: for m-pair mp (m0=2mp, m1=2mp+1):
    //  A0[k*8+mp] = (m0.d0, m0.d1, m0.d2, m0.d3)
    //  A1[k*8+mp] = (m0.d4, m0.d5, m1.d0, m1.d1)
    //  A2[k*8+mp] = (m1.d2, m1.d3, m1.d4, m1.d5)
    // 8 distinct lane addresses x 16B = 128B -> 1 wavefront per LDS.128
    // (4-way broadcast across row-groups). 12KB total.
    __shared__ float4 A0[K_CODES * NMP];
    __shared__ float4 A1[K_CODES * NMP];
    __shared__ float4 A2[K_CODES * NMP];

    const int t = threadIdx.x;
    const int grp = blockIdx.x / BLK_PER_G;
    const int bstart = blockIdx.x % BLK_PER_G;

    // One-time codebook repack for this group's 16 m's.
    {
        const float* cbg = cb + (size_t)grp * QM * (K_CODES * D_SUB);
        for (int i = t; i < NMP * K_CODES; i += TPB) {
            int mp = i >> 5;             // 0..7
            int k  = i & 31;
            const float* s0 = cbg + (size_t)(2 * mp) * (K_CODES * D_SUB) + k * D_SUB;
            const float* s1 = s0 + K_CODES * D_SUB;
            A0[k * NMP + mp] = make_float4(s0[0], s0[1], s0[2], s0[3]);
            A1[k * NMP + mp] = make_float4(s0[4], s0[5], s1[0], s1[1]);
            A2[k * NMP + mp] = make_float4(s1[2], s1[3], s1[4], s1[5]);
        }
    }
    __syncthreads();

    const int mp   = t & (NMP - 1);
    const int g    = t >> 3;             // row-group 0..31
    const int col0 = (grp * QM + 2 * mp) * D_SUB;   // 12 contiguous floats

    const size_t step = (size_t)BLK_PER_G * TILE_ROWS * DIM;
    const float* xp = x   + (size_t)(bstart * TILE_ROWS + g) * DIM + col0;
    float*       op = out + (size_t)(bstart * TILE_ROWS + g) * DIM + col0;

    // Prologue: load first tile's 12 x floats (3x LDG.128, 16B-aligned).
    float4 xv0, xv1, xv2;
    {
        const float4* p = reinterpret_cast<const float4*>(xp);
        xv0 = p[0]; xv1 = p[1]; xv2 = p[2];
    }

    for (int tile = bstart; tile < NTILES; tile += BLK_PER_G) {
        // ---- Prefetch next tile's x (clamped on last tile).
        const float* nxp = (tile + BLK_PER_G < NTILES) ? (xp + step) : xp;
        float4 nx0, nx1, nx2;
        {
            const float4* p = reinterpret_cast<const float4*>(nxp);
            nx0 = p[0]; nx1 = p[1]; nx2 = p[2];
        }

        // ---- Argmax over 32 codewords for both m's of the pair.
        float best0 = -CUDART_INF_F, best1 = -CUDART_INF_F;
        int   idx0 = 0, idx1 = 0;

        #pragma unroll 2
        for (int k = 0; k < K_CODES; k++) {
            const float4 a0 = A0[k * NMP + mp];
            const float4 a1 = A1[k * NMP + mp];
            const float4 a2 = A2[k * NMP + mp];
            // m0: frozen chain over d0..d5
            float d0 = xv0.x * a0.x;
            d0 = fmaf(xv0.y, a0.y, d0);
            d0 = fmaf(xv0.z, a0.z, d0);
            d0 = fmaf(xv0.w, a0.w, d0);
            d0 = fmaf(xv1.x, a1.x, d0);
            d0 = fmaf(xv1.y, a1.y, d0);
            // m1: frozen chain over d0..d5
            float d1 = xv1.z * a1.z;
            d1 = fmaf(xv1.w, a1.w, d1);
            d1 = fmaf(xv2.x, a2.x, d1);
            d1 = fmaf(xv2.y, a2.y, d1);
            d1 = fmaf(xv2.z, a2.z, d1);
            d1 = fmaf(xv2.w, a2.w, d1);
            // EXACT argmax, FIRST-max tie rule; FMNMX value chain keeps the
            // predicate latency off the loop-carried path.
            bool p0 = d0 > best0;
            best0 = fmaxf(best0, d0);
            idx0  = p0 ? k : idx0;
            bool p1 = d1 > best1;
            best1 = fmaxf(best1, d1);
            idx1  = p1 ? k : idx1;
        }

        // ---- Emit both winning codewords: 12 contiguous floats, 3x STG.128.
        {
            const float4 e0 = A0[idx0 * NMP + mp];
            const float2 e1a = *reinterpret_cast<const float2*>(&A1[idx0 * NMP + mp]);      // m0.d4, m0.d5
            const float2 e1b = *(reinterpret_cast<const float2*>(&A1[idx1 * NMP + mp]) + 1); // m1.d0, m1.d1
            const float4 e2 = A2[idx1 * NMP + mp];
            float4* po = reinterpret_cast<float4*>(op);
            po[0] = e0;
            po[1] = make_float4(e1a.x, e1a.y, e1b.x, e1b.y);
            po[2] = e2;
        }

        // ---- Rotate prefetched registers in.
        xv0 = nx0; xv1 = nx1; xv2 = nx2;
        xp = nxp;
        op += step;
    }
}

extern "C" void kernel_launch(void* const* d_in, const int* in_sizes, int n_in,
                              void* d_out, int out_size)
{
    const float* x  = (const float*)d_in[0];
    const float* cb = (const float*)d_in[1];
    float* out      = (float*)d_out;

    pq_head_kernel<<<NBLOCKS, TPB>>>(x, cb, out);
}

// round 14
// speedup vs baseline: 1.6634x; 1.6634x over previous
#include <cuda_runtime.h>
#include <math_constants.h>
#include <stdint.h>

// PQHead: out[b, m*6+d] = codebooks[m, argmax_k <x[b,m*6:...], cb[m,k,:]>, d]
// (forward value of the straight-through estimator == discrete codeword)
//
// FROZEN NUMERICS: dot = x0*c0 then fma.rn chain d=1..5 (scalar FFMA), argmax
// exact, FIRST-max tie rule. Zero flips vs JAX reference at this order.
//
// LESSONS:
//  R3/R4 spills, R7 f32x2 half-rate, R12 cp.async, R13 m-pair LDS.128 banned.
//  LDS law: smem wavefronts are lane-slot based (.32=1,.64=2,.128=4) -- the
//  codebook costs 6/RPT wf per (b,m) pair no matter the layout.
//  R8 (RPT=4, 32 warps, no prefetch): 64.7us, issue 62% -- tile-head LDG
//  stalls. R9 (RPT=2 + reg prefetch): 63us, LDS-bound (L1 84%).
//  R14 = R8 + prefetch.global.L1 of the next tile: register-free prefetch
//  unlocks RPT=4 + 32 warps + prefetch simultaneously.

#define B_ROWS   32768
#define M_SUB    128
#define QM       16                      // m's per block (1/8 split)
#define NGRP     (M_SUB / QM)            // 8
#define K_CODES  32
#define D_SUB    6
#define DIM      768
#define RPT      4                       // rows per thread
#define TPB      256                     // 16 row-groups x 16 m
#define TILE_ROWS (RPT * (TPB / QM))     // 64
#define NTILES   (B_ROWS / TILE_ROWS)    // 512 per group
#define BLK_PER_G 74                     // 8 groups x 74 = 592 = 4/SM
#define NBLOCKS  (NGRP * BLK_PER_G)

__global__ void __launch_bounds__(TPB, 4)
pq_head_kernel(const float* __restrict__ x,
               const float* __restrict__ cb,
               float* __restrict__ out)
{
    // Codebook split: cbA[k*16+m] = (d0,d1,d2,d3), cbB[k*16+m] = (d4,d5).
    // 12KB/CTA -> 48KB/SM at 4 CTAs, leaving ~180KB L1D for x tiles.
    __shared__ float4 cbA[K_CODES * QM];     // 8KB
    __shared__ float2 cbB[K_CODES * QM];     // 4KB

    const int t = threadIdx.x;
    const int grp = blockIdx.x / BLK_PER_G;      // which m-group this block owns
    const int bstart = blockIdx.x % BLK_PER_G;

    // One-time codebook load for this group.
    {
        const float* cbg = cb + (size_t)grp * QM * (K_CODES * D_SUB);
        for (int i = t; i < QM * K_CODES; i += TPB) {
            int mloc = i / K_CODES;
            int k    = i - mloc * K_CODES;
            const float* src = cbg + (size_t)mloc * (K_CODES * D_SUB) + k * D_SUB;
            cbA[k * QM + mloc] = make_float4(src[0], src[1], src[2], src[3]);
            cbB[k * QM + mloc] = make_float2(src[4], src[5]);
        }
    }
    __syncthreads();

    const int mloc = t & (QM - 1);
    const int g    = t >> 4;             // row-group 0..15
    const int col0 = (grp * QM + mloc) * D_SUB;

    // Running pointers (advance by BLK_PER_G tiles each iteration).
    const float* xp = x   + (size_t)(bstart * TILE_ROWS + g * RPT) * DIM + col0;
    float*       op = out + (size_t)(bstart * TILE_ROWS + g * RPT) * DIM + col0;
    const size_t step = (size_t)BLK_PER_G * TILE_ROWS * DIM;

    for (int tile = bstart; tile < NTILES; tile += BLK_PER_G) {
        // Batch-load RPT rows' 6-float subvectors (3x LDG.64 each).
        // First tile of each block misses to DRAM; subsequent tiles hit L1
        // thanks to the prefetch below.
        float xv[RPT][D_SUB];
        #pragma unroll
        for (int r = 0; r < RPT; r++) {
            const float2* p = reinterpret_cast<const float2*>(xp + (size_t)r * DIM);
            float2 a = p[0], bq = p[1], c = p[2];
            xv[r][0] = a.x;  xv[r][1] = a.y;
            xv[r][2] = bq.x; xv[r][3] = bq.y;
            xv[r][4] = c.x;  xv[r][5] = c.y;
        }

        // Register-free prefetch of the NEXT tile into L1. The warp's 16
        // lanes (24B apart) collectively touch every 128B line of each
        // row's 384B slice; one prefetch per row per thread suffices.
        if (tile + BLK_PER_G < NTILES) {
            const float* nxp = xp + step;
            #pragma unroll
            for (int r = 0; r < RPT; r++)
                asm volatile("prefetch.global.L1 [%0];"
                             :: "l"(nxp + (size_t)r * DIM));
        }

        float best[RPT];
        int   idx[RPT];
        #pragma unroll
        for (int r = 0; r < RPT; r++) { best[r] = -CUDART_INF_F; idx[r] = 0; }

        // Bounded unroll keeps live set ~61-64 regs (no spills).
        #pragma unroll 4
        for (int k = 0; k < K_CODES; k++) {
            const float4 ca  = cbA[k * QM + mloc];
            const float2 cbv = cbB[k * QM + mloc];
            #pragma unroll
            for (int r = 0; r < RPT; r++) {
                float dot = xv[r][0] * ca.x;
                dot = fmaf(xv[r][1], ca.y, dot);
                dot = fmaf(xv[r][2], ca.z, dot);
                dot = fmaf(xv[r][3], ca.w, dot);
                dot = fmaf(xv[r][4], cbv.x, dot);
                dot = fmaf(xv[r][5], cbv.y, dot);
                // EXACT argmax, FIRST-max tie rule. FMNMX value chain keeps
                // the 13-cyc predicate latency off the loop-carried path.
                bool p  = dot > best[r];
                best[r] = fmaxf(best[r], dot);
                idx[r]  = p ? k : idx[r];
            }
        }

        // Emit the winning codeword rows.
        #pragma unroll
        for (int r = 0; r < RPT; r++) {
            const float4 oa = cbA[idx[r] * QM + mloc];
            const float2 ob = cbB[idx[r] * QM + mloc];
            float2* po = reinterpret_cast<float2*>(op + (size_t)r * DIM);
            po[0] = make_float2(oa.x, oa.y);
            po[1] = make_float2(oa.z, oa.w);
            po[2] = ob;
        }

        xp += step;
        op += step;
    }
}

extern "C" void kernel_launch(void* const* d_in, const int* in_sizes, int n_in,
                              void* d_out, int out_size)
{
    const float* x  = (const float*)d_in[0];
    const float* cb = (const float*)d_in[1];
    float* out      = (float*)d_out;

    pq_head_kernel<<<NBLOCKS, TPB>>>(x, cb, out);
}